// round 7
// baseline (speedup 1.0000x reference)
#include <cuda_runtime.h>

#define INV_DQ4 0.35355339059327373f

#define BB   8
#define ST   2048
#define SMM  1024
#define DDIM 512
#define NHH  2
#define DKK  64
#define DHI  1024
#define TOK  (BB*ST)     /* 16384 */
#define TOKM (BB*SMM)    /* 8192  */
#define PERB (ST*DDIM)   /* 1048576 */

// ------------------------- static device scratch -------------------------
__device__ float g_y[TOK*DDIM];
__device__ float g_qkv[TOK*384];
__device__ float g_qx[TOK*128];
__device__ float g_kv[TOKM*256];
__device__ float g_zz[TOK*128];
__device__ float g_hid[TOK*DHI];
__device__ float g_w1[DDIM*DHI];
__device__ float g_w2[DHI*DDIM];
__device__ float g_wp[DDIM*384];
__device__ float g_bp[384];
__device__ float g_qm[BB*128], g_qz[BB*128];
__device__ float g_km[BB*128], g_kz[BB*128];
__device__ float g_bm[NHH*BB*64*64];
__device__ float g_part[BB*32*2];
__device__ float g_stat[BB*2];

// ------------------------- generic SGEMM (tiled) -------------------------
// C[M,N] = A[M,K] @ W[K,N] (+bias)(+swish)(+res). Requires M%BM==0, N covered
// by grid, K%BK==0, lda/ldw/ldc multiples of 4.
template<int BM, int BN, int BK, int TM, int TN>
__global__ void __launch_bounds__(256) sgemm_k(
    const float* __restrict__ A, int lda,
    const float* __restrict__ W, int ldw,
    float* __restrict__ C, int ldc, int K,
    const float* __restrict__ bias,
    const float* __restrict__ res, int act)
{
    __shared__ float As[BK][BM];
    __shared__ float Bs[BK][BN];
    const int tid  = threadIdx.x;
    const int row0 = blockIdx.y * BM;
    const int col0 = blockIdx.x * BN;
    const int ar = tid / (BK/4);
    const int ac = (tid % (BK/4)) * 4;
    const int br = tid / (BN/4);
    const int bc = (tid % (BN/4)) * 4;
    const int tx = tid % (BN/TN);
    const int ty = tid / (BN/TN);

    float acc[TM][TN];
    #pragma unroll
    for (int i = 0; i < TM; i++)
        #pragma unroll
        for (int j = 0; j < TN; j++) acc[i][j] = 0.f;

    const float* Ap = A + (long)(row0 + ar) * lda + ac;
    const float* Wp = W + (long)br * ldw + col0 + bc;

    for (int k0 = 0; k0 < K; k0 += BK) {
        float4 a4 = *(const float4*)(Ap + k0);
        As[ac+0][ar] = a4.x; As[ac+1][ar] = a4.y;
        As[ac+2][ar] = a4.z; As[ac+3][ar] = a4.w;
        float4 b4 = *(const float4*)(Wp + (long)k0 * ldw);
        *(float4*)&Bs[br][bc] = b4;
        __syncthreads();
        #pragma unroll
        for (int kk = 0; kk < BK; kk++) {
            float ra[TM], rb[TN];
            #pragma unroll
            for (int i = 0; i < TM; i += 4)
                *(float4*)&ra[i] = *(const float4*)&As[kk][ty*TM + i];
            #pragma unroll
            for (int j = 0; j < TN; j += 4)
                *(float4*)&rb[j] = *(const float4*)&Bs[kk][tx*TN + j];
            #pragma unroll
            for (int i = 0; i < TM; i++)
                #pragma unroll
                for (int j = 0; j < TN; j++)
                    acc[i][j] += ra[i] * rb[j];
        }
        __syncthreads();
    }

    #pragma unroll
    for (int i = 0; i < TM; i++) {
        int r = row0 + ty*TM + i;
        #pragma unroll
        for (int j = 0; j < TN; j++) {
            int c = col0 + tx*TN + j;
            float v = acc[i][j];
            if (bias) v += bias[c];
            if (act)  v = v / (1.f + __expf(-v));   // swish
            if (res)  v += res[(long)r * ldc + c];
            C[(long)r * ldc + c] = v;
        }
    }
}

// ------------------------- weight/bias packing -------------------------
// wp[d][j], j = part*128 + h*64 + e : part 0=Q, 1=K, 2=V. Wsrc is (h,d,e).
__global__ void pack_qkv(const float* __restrict__ Wq, const float* __restrict__ Wk,
                         const float* __restrict__ Wv, const float* __restrict__ bq,
                         const float* __restrict__ bk, const float* __restrict__ bv,
                         float* __restrict__ wp, float* __restrict__ bp)
{
    int idx = blockIdx.x * blockDim.x + threadIdx.x;
    if (idx < DDIM * 384) {
        int d = idx / 384, j = idx % 384;
        int p = j >> 7, jj = j & 127;
        int h = jj >> 6, e = jj & 63;
        const float* src = (p == 0) ? Wq : (p == 1) ? Wk : Wv;
        wp[idx] = src[((long)h * DDIM + d) * DKK + e];
    }
    if (idx < 384) {
        int p = idx >> 7, jj = idx & 127;
        const float* sb = (p == 0) ? bq : (p == 1) ? bk : bv;
        bp[idx] = sb[jj];
    }
}

// ------------------------- column softmax stats -------------------------
// per (b, j): max & sum-exp over s of X[b*S+s, coloff+j]*INV_DQ4.
// mask=1 (causal self-attn): only s >= e (e = j%64) participate.
__global__ void colstat(const float* __restrict__ X, int ld, int coloff,
                        int S, int mask, float* __restrict__ m_out,
                        float* __restrict__ z_out)
{
    int j = blockIdx.x, b = blockIdx.y;
    int e = j & 63;
    const float* base = X + (long)b * S * ld + coloff + j;
    int s0 = mask ? e : 0;
    __shared__ float red[256];
    float mx = -1e30f;
    for (int s = s0 + threadIdx.x; s < S; s += 256)
        mx = fmaxf(mx, base[(long)s * ld] * INV_DQ4);
    red[threadIdx.x] = mx; __syncthreads();
    for (int st = 128; st > 0; st >>= 1) {
        if (threadIdx.x < st)
            red[threadIdx.x] = fmaxf(red[threadIdx.x], red[threadIdx.x + st]);
        __syncthreads();
    }
    mx = red[0];
    __syncthreads();
    float sum = 0.f;
    for (int s = s0 + threadIdx.x; s < S; s += 256)
        sum += __expf(base[(long)s * ld] * INV_DQ4 - mx);
    red[threadIdx.x] = sum; __syncthreads();
    for (int st = 128; st > 0; st >>= 1) {
        if (threadIdx.x < st) red[threadIdx.x] += red[threadIdx.x + st];
        __syncthreads();
    }
    if (threadIdx.x == 0) { m_out[b*128 + j] = mx; z_out[b*128 + j] = red[0]; }
}

// ------------------------- Bm[e,d] = softmax_s(K^T/dq4) @ V -------------------------
__global__ void __launch_bounds__(256) bm_kernel(
    const float* __restrict__ Kb, int ldk, int koff,
    const float* __restrict__ Vb, int ldv, int voff,
    int S, const float* __restrict__ km, const float* __restrict__ kz,
    float* __restrict__ bm)
{
    int blk = blockIdx.x;            // h*BB + b
    int h = blk / BB, b = blk % BB;
    int tid = threadIdx.x;
    int e  = tid >> 2;
    int d0 = (tid & 3) * 16;
    __shared__ float Ks[64][64];
    __shared__ float Vs[64][64];
    float acc[16];
    #pragma unroll
    for (int i = 0; i < 16; i++) acc[i] = 0.f;
    float me = km[b*128 + h*64 + e];
    const float* kp = Kb + (long)b * S * ldk + koff + h*64;
    const float* vp = Vb + (long)b * S * ldv + voff + h*64;
    for (int s0 = 0; s0 < S; s0 += 64) {
        for (int idx = tid; idx < 64*16; idx += 256) {
            int r = idx >> 4, c4 = (idx & 15) << 2;
            *(float4*)&Ks[r][c4] = *(const float4*)(kp + (long)(s0 + r) * ldk + c4);
            *(float4*)&Vs[r][c4] = *(const float4*)(vp + (long)(s0 + r) * ldv + c4);
        }
        __syncthreads();
        #pragma unroll 4
        for (int s = 0; s < 64; s++) {
            float w = __expf(Ks[s][e] * INV_DQ4 - me);
            #pragma unroll
            for (int dd = 0; dd < 16; dd++) acc[dd] += w * Vs[s][d0 + dd];
        }
        __syncthreads();
    }
    float inz = 1.f / kz[b*128 + h*64 + e];
    float* out = bm + ((long)blk * 64 + e) * 64 + d0;
    #pragma unroll
    for (int dd = 0; dd < 16; dd++) out[dd] = acc[dd] * inz;
}

// ------------------------- Z[s,:] = A[s,:] @ Bm (both heads) -------------------------
// 16 rows per block; thread = (rid, h, dq) computes 8 d-values.
__global__ void __launch_bounds__(256) z_kernel(
    const float* __restrict__ Q, int ldq,
    const float* __restrict__ bm,
    const float* __restrict__ qm, const float* __restrict__ qz,
    float* __restrict__ Z, int mask)
{
    __shared__ float Bs[2][64][64];   // 32 KB
    __shared__ float qs[16][128];     //  8 KB
    __shared__ float sm[128], siz[128];
    int tid  = threadIdx.x;
    int row0 = blockIdx.x * 16;
    int b    = row0 / ST;
    for (int idx = tid; idx < 2048; idx += 256) {   // Bm both heads (float4)
        int hh = idx >> 10;
        int rr = (idx >> 4) & 63;
        int c4 = (idx & 15) << 2;
        *(float4*)&Bs[hh][rr][c4] =
            *(const float4*)(bm + ((long)(hh*BB + b) * 64 + rr) * 64 + c4);
    }
    for (int idx = tid; idx < 512; idx += 256) {    // 16x128 q rows (float4)
        int rr = idx >> 5, c4 = (idx & 31) << 2;
        *(float4*)&qs[rr][c4] = *(const float4*)(Q + (long)(row0 + rr) * ldq + c4);
    }
    if (tid < 128) { sm[tid] = qm[b*128 + tid]; siz[tid] = 1.f / qz[b*128 + tid]; }
    __syncthreads();

    int rid = tid >> 4;
    int sub = tid & 15;
    int h   = sub >> 3;
    int d0  = (sub & 7) * 8;
    int s   = (row0 + rid) & (ST - 1);
    float acc[8];
    #pragma unroll
    for (int i = 0; i < 8; i++) acc[i] = 0.f;
    int elim = mask ? min(63, s) : 63;
    for (int e = 0; e <= elim; e++) {
        float w = __expf(qs[rid][h*64 + e] * INV_DQ4 - sm[h*64 + e]) * siz[h*64 + e];
        const float* bp = &Bs[h][e][d0];
        #pragma unroll
        for (int dd = 0; dd < 8; dd++) acc[dd] += w * bp[dd];
    }
    float* out = Z + (long)(row0 + rid) * 128 + h*64 + d0;
    #pragma unroll
    for (int dd = 0; dd < 8; dd++) out[dd] = acc[dd];
}

// ------------------------- LayerNorm (per batch over S*D) -------------------------
__global__ void ln_part(const float* __restrict__ X, float* __restrict__ part)
{
    int b = blockIdx.y, chunk = blockIdx.x;   // 32 chunks of 8192 float4
    const float4* p = (const float4*)(X + (long)b * PERB) + (long)chunk * 8192 + threadIdx.x;
    float s = 0.f, q = 0.f;
    for (int k = 0; k < 32; k++) {
        float4 v = p[(long)k * 256];
        s += v.x + v.y + v.z + v.w;
        q += v.x*v.x + v.y*v.y + v.z*v.z + v.w*v.w;
    }
    __shared__ float rs[256], rq[256];
    rs[threadIdx.x] = s; rq[threadIdx.x] = q; __syncthreads();
    for (int st = 128; st > 0; st >>= 1) {
        if (threadIdx.x < st) {
            rs[threadIdx.x] += rs[threadIdx.x + st];
            rq[threadIdx.x] += rq[threadIdx.x + st];
        }
        __syncthreads();
    }
    if (threadIdx.x == 0) {
        part[(b*32 + chunk)*2]     = rs[0];
        part[(b*32 + chunk)*2 + 1] = rq[0];
    }
}

__global__ void ln_final(const float* __restrict__ part, float* __restrict__ stat)
{
    int b = blockIdx.x;
    float s = part[(b*32 + threadIdx.x)*2];
    float q = part[(b*32 + threadIdx.x)*2 + 1];
    for (int o = 16; o > 0; o >>= 1) {
        s += __shfl_down_sync(0xffffffffu, s, o);
        q += __shfl_down_sync(0xffffffffu, q, o);
    }
    if (threadIdx.x == 0) {
        float mean = s / (float)PERB;
        float var  = q / (float)PERB - mean * mean;
        stat[b*2] = mean; stat[b*2 + 1] = rsqrtf(var + 1e-5f);
    }
}

__global__ void ln_apply(const float* __restrict__ X, const float* __restrict__ g,
                         const float* __restrict__ bt, const float* __restrict__ stat,
                         float* __restrict__ out)
{
    long i4  = (long)blockIdx.x * blockDim.x + threadIdx.x;
    long idx = i4 * 4;
    int  b   = (int)(idx / PERB);
    long gi  = idx % PERB;
    float mean = stat[b*2], rstd = stat[b*2 + 1];
    float4 x  = *(const float4*)(X + idx);
    float4 gg = *(const float4*)(g + gi);
    float4 bb = *(const float4*)(bt + gi);
    float4 o;
    o.x = (x.x - mean) * rstd * gg.x + bb.x;
    o.y = (x.y - mean) * rstd * gg.y + bb.y;
    o.z = (x.z - mean) * rstd * gg.z + bb.z;
    o.w = (x.w - mean) * rstd * gg.w + bb.w;
    *(float4*)(out + idx) = o;
}

__global__ void copy_f4(const float* __restrict__ src, float* __restrict__ dst)
{
    long i = (long)blockIdx.x * blockDim.x + threadIdx.x;
    ((float4*)dst)[i] = ((const float4*)src)[i];
}

// ------------------------- host orchestration -------------------------
extern "C" void kernel_launch(void* const* d_in, const int* in_sizes, int n_in,
                              void* d_out, int out_size)
{
    (void)in_sizes; (void)n_in; (void)out_size;
    const float* mem   = (const float*)d_in[0];
    const float* y_in  = (const float*)d_in[1];
    const float* Wq_sa = (const float*)d_in[2];
    const float* bq_sa = (const float*)d_in[3];
    const float* Wk_sa = (const float*)d_in[4];
    const float* bk_sa = (const float*)d_in[5];
    const float* Wv_sa = (const float*)d_in[6];
    const float* bv_sa = (const float*)d_in[7];
    const float* Wo_sa = (const float*)d_in[8];
    const float* bo_sa = (const float*)d_in[9];
    const float* Wq_x  = (const float*)d_in[10];
    const float* bq_x  = (const float*)d_in[11];
    const float* Wk_x  = (const float*)d_in[12];
    const float* bk_x  = (const float*)d_in[13];
    const float* Wv_x  = (const float*)d_in[14];
    const float* bv_x  = (const float*)d_in[15];
    const float* Wo_x  = (const float*)d_in[16];
    const float* bo_x  = (const float*)d_in[17];
    const float* E1    = (const float*)d_in[18];
    const float* D1    = (const float*)d_in[19];
    const float* E2    = (const float*)d_in[20];
    const float* D2    = (const float*)d_in[21];
    const float* g1    = (const float*)d_in[22];
    const float* b1    = (const float*)d_in[23];
    const float* g2    = (const float*)d_in[24];
    const float* b2    = (const float*)d_in[25];
    const float* g3    = (const float*)d_in[26];
    const float* b3    = (const float*)d_in[27];
    float* out = (float*)d_out;

    float *yp,*qkv,*qx,*kv,*zz,*hid,*w1,*w2,*wp,*bp,*qm,*qz,*km,*kz,*bm,*part,*stat;
    cudaGetSymbolAddress((void**)&yp,   g_y);
    cudaGetSymbolAddress((void**)&qkv,  g_qkv);
    cudaGetSymbolAddress((void**)&qx,   g_qx);
    cudaGetSymbolAddress((void**)&kv,   g_kv);
    cudaGetSymbolAddress((void**)&zz,   g_zz);
    cudaGetSymbolAddress((void**)&hid,  g_hid);
    cudaGetSymbolAddress((void**)&w1,   g_w1);
    cudaGetSymbolAddress((void**)&w2,   g_w2);
    cudaGetSymbolAddress((void**)&wp,   g_wp);
    cudaGetSymbolAddress((void**)&bp,   g_bp);
    cudaGetSymbolAddress((void**)&qm,   g_qm);
    cudaGetSymbolAddress((void**)&qz,   g_qz);
    cudaGetSymbolAddress((void**)&km,   g_km);
    cudaGetSymbolAddress((void**)&kz,   g_kz);
    cudaGetSymbolAddress((void**)&bm,   g_bm);
    cudaGetSymbolAddress((void**)&part, g_part);
    cudaGetSymbolAddress((void**)&stat, g_stat);

    // residual stream init
    copy_f4<<<TOK*DDIM/4/256, 256>>>(y_in, yp);

    // ===== masked self-attention MHLA =====
    pack_qkv<<<(DDIM*384 + 255)/256, 256>>>(Wq_sa, Wk_sa, Wv_sa, bq_sa, bk_sa, bv_sa, wp, bp);
    sgemm_k<128,128,8,8,8><<<dim3(384/128, TOK/128), 256>>>(
        yp, DDIM, wp, 384, qkv, 384, DDIM, bp, nullptr, 0);
    colstat<<<dim3(128, BB), 256>>>(qkv, 384,   0, ST, 1, qm, qz);   // Q, causal
    colstat<<<dim3(128, BB), 256>>>(qkv, 384, 128, ST, 0, km, kz);   // K
    bm_kernel<<<NHH*BB, 256>>>(qkv, 384, 128, qkv, 384, 256, ST, km, kz, bm);
    z_kernel<<<TOK/16, 256>>>(qkv, 384, bm, qm, qz, zz, 1);
    sgemm_k<128,128,8,8,8><<<dim3(DDIM/128, TOK/128), 256>>>(
        zz, 128, Wo_sa, DDIM, yp, DDIM, 128, bo_sa, yp, 0);          // +residual
    ln_part<<<dim3(32, BB), 256>>>(yp, part);
    ln_final<<<BB, 32>>>(part, stat);
    ln_apply<<<TOK*DDIM/4/256, 256>>>(yp, g1, b1, stat, yp);

    // ===== cross-attention MHLA =====
    pack_qkv<<<(DDIM*384 + 255)/256, 256>>>(Wq_x, Wk_x, Wv_x, bq_x, bk_x, bv_x, wp, bp);
    sgemm_k<128,128,8,8,8><<<dim3(1, TOK/128), 256>>>(
        yp, DDIM, wp, 384, qx, 128, DDIM, bp, nullptr, 0);           // Q from y
    sgemm_k<128,128,8,8,8><<<dim3(2, TOKM/128), 256>>>(
        mem, DDIM, wp + 128, 384, kv, 256, DDIM, bp + 128, nullptr, 0); // K,V from mem
    colstat<<<dim3(128, BB), 256>>>(qx, 128, 0, ST,  0, qm, qz);
    colstat<<<dim3(128, BB), 256>>>(kv, 256, 0, SMM, 0, km, kz);
    bm_kernel<<<NHH*BB, 256>>>(kv, 256, 0, kv, 256, 128, SMM, km, kz, bm);
    z_kernel<<<TOK/16, 256>>>(qx, 128, bm, qm, qz, zz, 0);
    sgemm_k<128,128,8,8,8><<<dim3(DDIM/128, TOK/128), 256>>>(
        zz, 128, Wo_x, DDIM, yp, DDIM, 128, bo_x, yp, 0);            // +residual
    ln_part<<<dim3(32, BB), 256>>>(yp, part);
    ln_final<<<BB, 32>>>(part, stat);
    ln_apply<<<TOK*DDIM/4/256, 256>>>(yp, g2, b2, stat, yp);

    // ===== LFFN with fused bottleneck weights =====
    sgemm_k<64,64,16,4,4><<<dim3(DHI/64, DDIM/64), 256>>>(
        E1, ST, D1, DHI, w1, DHI, ST, nullptr, nullptr, 0);          // W1 = E1@D1
    sgemm_k<64,64,16,4,4><<<dim3(DDIM/64, DHI/64), 256>>>(
        E2, ST, D2, DDIM, w2, DDIM, ST, nullptr, nullptr, 0);        // W2 = E2@D2
    sgemm_k<128,128,8,8,8><<<dim3(DHI/128, TOK/128), 256>>>(
        yp, DDIM, w1, DHI, hid, DHI, DDIM, nullptr, nullptr, 1);     // swish
    sgemm_k<128,128,8,8,8><<<dim3(DDIM/128, TOK/128), 256>>>(
        hid, DHI, w2, DDIM, yp, DDIM, DHI, nullptr, yp, 0);          // +residual
    ln_part<<<dim3(32, BB), 256>>>(yp, part);
    ln_final<<<BB, 32>>>(part, stat);
    ln_apply<<<TOK*DDIM/4/256, 256>>>(yp, g3, b3, stat, out);        // final -> d_out
}

// round 12
// speedup vs baseline: 1.5421x; 1.5421x over previous
#include <cuda_runtime.h>
#include <cuda_bf16.h>
#include <cstdint>
typedef __nv_bfloat16 bf16;

#define INV_DQ4 0.35355339059327373f
#define BB   8
#define ST   2048
#define SMM  1024
#define DDIM 512
#define DHI  1024
#define TOK  16384
#define TOKM 8192
#define PERB (ST*DDIM)

// ---------------- scratch ----------------
__device__ float g_y[TOK*DDIM];
__device__ float g_qkv[TOK*384];
__device__ float g_qx[TOK*128];
__device__ float g_kv[TOKM*256];
__device__ float g_zz[TOK*128];
__device__ float g_hid[TOK*DHI];
__device__ float g_w1[DDIM*DHI];
__device__ float g_w2[DHI*DDIM];
__device__ float g_wp[DDIM*384];
__device__ float g_bp[384];
__device__ float g_qm[BB*128], g_qz[BB*128];
__device__ float g_km[BB*128], g_kz[BB*128];
__device__ float g_bm[16*4096];
__device__ float g_part[BB*32*2];
__device__ float g_stat[BB*2];
__device__ bf16  g_ah[TOK*DHI], g_al[TOK*DHI];   // A hi/lo
__device__ bf16  g_bh[DHI*ST],  g_bl[DHI*ST];    // B hi/lo

// ---------------- split: fp32 -> bf16 hi/lo ----------------
__global__ void splitf(const float* __restrict__ src, bf16* __restrict__ hi,
                       bf16* __restrict__ lo, int n8)
{
    int i = blockIdx.x * 256 + threadIdx.x;
    if (i >= n8) return;
    float4 a = ((const float4*)src)[(long)i*2];
    float4 b = ((const float4*)src)[(long)i*2 + 1];
    float v[8] = {a.x,a.y,a.z,a.w,b.x,b.y,b.z,b.w};
    bf16 h[8], l[8];
    #pragma unroll
    for (int k = 0; k < 8; k++) {
        h[k] = __float2bfloat16(v[k]);
        l[k] = __float2bfloat16(v[k] - __bfloat162float(h[k]));
    }
    ((uint4*)hi)[i] = *(uint4*)h;
    ((uint4*)lo)[i] = *(uint4*)l;
}

// W[K][N] fp32 -> T[N][K] bf16 hi/lo  (K,N multiples of 32)
__global__ void tsplit(const float* __restrict__ W, int K, int N,
                       bf16* __restrict__ Th, bf16* __restrict__ Tl)
{
    __shared__ float t[32][33];
    int k0 = blockIdx.x * 32, n0 = blockIdx.y * 32;
    for (int i = threadIdx.y; i < 32; i += 8)
        t[i][threadIdx.x] = W[(long)(k0 + i) * N + n0 + threadIdx.x];
    __syncthreads();
    for (int i = threadIdx.y; i < 32; i += 8) {
        float v = t[threadIdx.x][i];
        bf16 h = __float2bfloat16(v);
        long o = (long)(n0 + i) * K + k0 + threadIdx.x;
        Th[o] = h;
        Tl[o] = __float2bfloat16(v - __bfloat162float(h));
    }
}

// ---------------- bf16-split tensor-core GEMM ----------------
#define MMA_BF16(d, a, b) asm volatile( \
    "mma.sync.aligned.m16n8k16.row.col.f32.bf16.bf16.f32 " \
    "{%0,%1,%2,%3}, {%4,%5,%6,%7}, {%8,%9}, {%0,%1,%2,%3};" \
    : "+f"(d[0]), "+f"(d[1]), "+f"(d[2]), "+f"(d[3]) \
    : "r"(a[0]), "r"(a[1]), "r"(a[2]), "r"(a[3]), "r"(b[0]), "r"(b[1]))

// C[M,N] = (Ah+Al)[M,K] @ (Bh+Bl)[N,K]^T ; K % 32 == 0.
template<int BM, int BN, int WM, int WN>
__global__ void __launch_bounds__((BM/WM)*(BN/WN)*32) mma_gemm(
    const bf16* __restrict__ Ah, const bf16* __restrict__ Al,
    const bf16* __restrict__ Bh, const bf16* __restrict__ Bl,
    int K, float* __restrict__ C, int ldc,
    const float* __restrict__ bias, const float* __restrict__ res, int act)
{
    constexpr int NWN = BN / WN;
    constexpr int NT  = (BM/WM) * NWN * 32;
    constexpr int MT  = WM / 16, NTL = WN / 8;
    constexpr int RW  = 20;
    __shared__ uint32_t sA[2*BM*RW];
    __shared__ uint32_t sB[2*BN*RW];
    const int tid = threadIdx.x, wid = tid >> 5, lane = tid & 31;
    const int wm = wid / NWN, wn = wid % NWN;
    const int lq = lane & 3, lr = lane >> 2;
    const long row0 = (long)blockIdx.y * BM;
    const long col0 = (long)blockIdx.x * BN;
    constexpr int ITA = (BM*4) / NT, ITB = (BN*4) / NT;
    uint4 rah[ITA], ral[ITA], rbh[ITB], rbl[ITB];

    auto ldg = [&](int k0) {
        #pragma unroll
        for (int i = 0; i < ITA; i++) {
            int idx = tid + i*NT;
            long off = (row0 + (idx>>2)) * (long)K + k0 + ((idx&3)<<3);
            rah[i] = *(const uint4*)(Ah + off);
            ral[i] = *(const uint4*)(Al + off);
        }
        #pragma unroll
        for (int i = 0; i < ITB; i++) {
            int idx = tid + i*NT;
            long off = (col0 + (idx>>2)) * (long)K + k0 + ((idx&3)<<3);
            rbh[i] = *(const uint4*)(Bh + off);
            rbl[i] = *(const uint4*)(Bl + off);
        }
    };
    auto sts = [&]() {
        #pragma unroll
        for (int i = 0; i < ITA; i++) {
            int idx = tid + i*NT;
            int w = (idx>>2)*RW + ((idx&3)<<2);
            *(uint4*)&sA[w] = rah[i];
            *(uint4*)&sA[BM*RW + w] = ral[i];
        }
        #pragma unroll
        for (int i = 0; i < ITB; i++) {
            int idx = tid + i*NT;
            int w = (idx>>2)*RW + ((idx&3)<<2);
            *(uint4*)&sB[w] = rbh[i];
            *(uint4*)&sB[BN*RW + w] = rbl[i];
        }
    };

    float acc[MT][NTL][4];
    #pragma unroll
    for (int i = 0; i < MT; i++)
        #pragma unroll
        for (int j = 0; j < NTL; j++) {
            acc[i][j][0]=0.f; acc[i][j][1]=0.f; acc[i][j][2]=0.f; acc[i][j][3]=0.f;
        }

    auto compute = [&]() {
        #pragma unroll
        for (int ks = 0; ks < 2; ks++) {
            const int kw = ks * 8;
            uint32_t afh[MT][4], afl[MT][4], bfh[NTL][2], bfl[NTL][2];
            #pragma unroll
            for (int i = 0; i < MT; i++) {
                int base = (wm*WM + i*16 + lr)*RW + kw + lq;
                afh[i][0]=sA[base];          afh[i][1]=sA[base+8*RW];
                afh[i][2]=sA[base+4];        afh[i][3]=sA[base+8*RW+4];
                afl[i][0]=sA[BM*RW+base];    afl[i][1]=sA[BM*RW+base+8*RW];
                afl[i][2]=sA[BM*RW+base+4];  afl[i][3]=sA[BM*RW+base+8*RW+4];
            }
            #pragma unroll
            for (int j = 0; j < NTL; j++) {
                int base = (wn*WN + j*8 + lr)*RW + kw + lq;
                bfh[j][0]=sB[base];        bfh[j][1]=sB[base+4];
                bfl[j][0]=sB[BN*RW+base];  bfl[j][1]=sB[BN*RW+base+4];
            }
            #pragma unroll
            for (int i = 0; i < MT; i++)
                #pragma unroll
                for (int j = 0; j < NTL; j++) {
                    MMA_BF16(acc[i][j], afh[i], bfh[j]);
                    MMA_BF16(acc[i][j], afh[i], bfl[j]);
                    MMA_BF16(acc[i][j], afl[i], bfh[j]);
                }
        }
    };

    ldg(0); sts(); __syncthreads();
    for (int k0 = 32; k0 < K; k0 += 32) {
        ldg(k0);
        compute();
        __syncthreads();
        sts();
        __syncthreads();
    }
    compute();

    #pragma unroll
    for (int i = 0; i < MT; i++) {
        int r = (int)row0 + wm*WM + i*16 + lr;
        #pragma unroll
        for (int j = 0; j < NTL; j++) {
            int cb = (int)col0 + wn*WN + j*8 + 2*lq;
            float v[4] = {acc[i][j][0], acc[i][j][1], acc[i][j][2], acc[i][j][3]};
            if (bias) { float b0 = bias[cb], b1 = bias[cb+1];
                        v[0]+=b0; v[1]+=b1; v[2]+=b0; v[3]+=b1; }
            if (act) {
                #pragma unroll
                for (int q = 0; q < 4; q++) v[q] = v[q] / (1.f + __expf(-v[q]));
            }
            long o0 = (long)r*ldc + cb, o1 = (long)(r+8)*ldc + cb;
            if (res) { v[0]+=res[o0]; v[1]+=res[o0+1]; v[2]+=res[o1]; v[3]+=res[o1+1]; }
            *(float2*)(C + o0) = make_float2(v[0], v[1]);
            *(float2*)(C + o1) = make_float2(v[2], v[3]);
        }
    }
}

// ---------------- QKV weight packing ----------------
__global__ void pack_qkv(const float* __restrict__ Wq, const float* __restrict__ Wk,
                         const float* __restrict__ Wv, const float* __restrict__ bq,
                         const float* __restrict__ bk, const float* __restrict__ bv,
                         float* __restrict__ wp, float* __restrict__ bp)
{
    int idx = blockIdx.x * blockDim.x + threadIdx.x;
    if (idx < DDIM * 384) {
        int d = idx / 384, j = idx % 384;
        int p = j >> 7, jj = j & 127;
        int h = jj >> 6, e = jj & 63;
        const float* src = (p == 0) ? Wq : (p == 1) ? Wk : Wv;
        wp[idx] = src[((long)h * DDIM + d) * 64 + e];
    }
    if (idx < 384) {
        int p = idx >> 7, jj = idx & 127;
        const float* sb = (p == 0) ? bq : (p == 1) ? bk : bv;
        bp[idx] = sb[jj];
    }
}

// ---------------- column softmax stats ----------------
__global__ void colstat(const float* __restrict__ X, int ld, int coloff,
                        int S, int mask, float* __restrict__ m_out,
                        float* __restrict__ z_out)
{
    int j = blockIdx.x, b = blockIdx.y;
    int e = j & 63;
    const float* base = X + (long)b * S * ld + coloff + j;
    int s0 = mask ? e : 0;
    __shared__ float red[256];
    float mx = -1e30f;
    for (int s = s0 + threadIdx.x; s < S; s += 256)
        mx = fmaxf(mx, base[(long)s * ld] * INV_DQ4);
    red[threadIdx.x] = mx; __syncthreads();
    for (int st = 128; st > 0; st >>= 1) {
        if (threadIdx.x < st)
            red[threadIdx.x] = fmaxf(red[threadIdx.x], red[threadIdx.x + st]);
        __syncthreads();
    }
    mx = red[0];
    __syncthreads();
    float sum = 0.f;
    for (int s = s0 + threadIdx.x; s < S; s += 256)
        sum += __expf(base[(long)s * ld] * INV_DQ4 - mx);
    red[threadIdx.x] = sum; __syncthreads();
    for (int st = 128; st > 0; st >>= 1) {
        if (threadIdx.x < st) red[threadIdx.x] += red[threadIdx.x + st];
        __syncthreads();
    }
    if (threadIdx.x == 0) { m_out[b*128 + j] = mx; z_out[b*128 + j] = red[0]; }
}

// ---------------- Bm = softmax_s(K^T) @ V ----------------
__global__ void __launch_bounds__(256) bm_kernel(
    const float* __restrict__ Kb, int ldk, int koff,
    const float* __restrict__ Vb, int ldv, int voff,
    int S, const float* __restrict__ km, const float* __restrict__ kz,
    float* __restrict__ bm)
{
    int blk = blockIdx.x;
    int h = blk / BB, b = blk % BB;
    int tid = threadIdx.x;
    int e = tid >> 2, d0 = (tid & 3) * 16;
    __shared__ float Ks[64][64];
    __shared__ float Vs[64][64];
    float acc[16];
    #pragma unroll
    for (int i = 0; i < 16; i++) acc[i] = 0.f;
    float me = km[b*128 + h*64 + e];
    const float* kp = Kb + (long)b * S * ldk + koff + h*64;
    const float* vp = Vb + (long)b * S * ldv + voff + h*64;
    for (int s0 = 0; s0 < S; s0 += 64) {
        for (int idx = tid; idx < 64*16; idx += 256) {
            int r = idx >> 4, c4 = (idx & 15) << 2;
            *(float4*)&Ks[r][c4] = *(const float4*)(kp + (long)(s0 + r) * ldk + c4);
            *(float4*)&Vs[r][c4] = *(const float4*)(vp + (long)(s0 + r) * ldv + c4);
        }
        __syncthreads();
        #pragma unroll 4
        for (int s = 0; s < 64; s++) {
            float w = __expf(Ks[s][e] * INV_DQ4 - me);
            #pragma unroll
            for (int dd = 0; dd < 16; dd++) acc[dd] += w * Vs[s][d0 + dd];
        }
        __syncthreads();
    }
    float inz = 1.f / kz[b*128 + h*64 + e];
    float* out = bm + ((long)blk * 64 + e) * 64 + d0;
    #pragma unroll
    for (int dd = 0; dd < 16; dd++) out[dd] = acc[dd] * inz;
}

// ---------------- Z = A @ Bm ----------------
__global__ void __launch_bounds__(256) z_kernel(
    const float* __restrict__ Q, int ldq, const float* __restrict__ bm,
    const float* __restrict__ qm, const float* __restrict__ qz,
    float* __restrict__ Z, int mask)
{
    __shared__ float Bs[2][64][64];
    __shared__ float qs[16][128];
    __shared__ float sm[128], siz[128];
    int tid = threadIdx.x;
    int row0 = blockIdx.x * 16;
    int b = row0 / ST;
    for (int idx = tid; idx < 2048; idx += 256) {
        int hh = idx >> 10, rr = (idx >> 4) & 63, c4 = (idx & 15) << 2;
        *(float4*)&Bs[hh][rr][c4] =
            *(const float4*)(bm + ((long)(hh*BB + b) * 64 + rr) * 64 + c4);
    }
    for (int idx = tid; idx < 512; idx += 256) {
        int rr = idx >> 5, c4 = (idx & 31) << 2;
        *(float4*)&qs[rr][c4] = *(const float4*)(Q + (long)(row0 + rr) * ldq + c4);
    }
    if (tid < 128) { sm[tid] = qm[b*128 + tid]; siz[tid] = 1.f / qz[b*128 + tid]; }
    __syncthreads();
    int rid = tid >> 4, sub = tid & 15;
    int h = sub >> 3, d0 = (sub & 7) * 8;
    int s = (row0 + rid) & (ST - 1);
    float acc[8];
    #pragma unroll
    for (int i = 0; i < 8; i++) acc[i] = 0.f;
    int elim = mask ? min(63, s) : 63;
    for (int e = 0; e <= elim; e++) {
        float w = __expf(qs[rid][h*64 + e] * INV_DQ4 - sm[h*64 + e]) * siz[h*64 + e];
        const float* bp = &Bs[h][e][d0];
        #pragma unroll
        for (int dd = 0; dd < 8; dd++) acc[dd] += w * bp[dd];
    }
    float* out = Z + (long)(row0 + rid) * 128 + h*64 + d0;
    #pragma unroll
    for (int dd = 0; dd < 8; dd++) out[dd] = acc[dd];
}

// ---------------- LayerNorm (per batch over S*D) ----------------
__global__ void ln_part(const float* __restrict__ X, float* __restrict__ part)
{
    int b = blockIdx.y, chunk = blockIdx.x;
    const float4* p = (const float4*)(X + (long)b*PERB) + (long)chunk*8192 + threadIdx.x;
    float s = 0.f, q = 0.f;
    for (int k = 0; k < 32; k++) {
        float4 v = p[(long)k*256];
        s += v.x + v.y + v.z + v.w;
        q += v.x*v.x + v.y*v.y + v.z*v.z + v.w*v.w;
    }
    __shared__ float rs[256], rq[256];
    rs[threadIdx.x] = s; rq[threadIdx.x] = q; __syncthreads();
    for (int st = 128; st > 0; st >>= 1) {
        if (threadIdx.x < st) {
            rs[threadIdx.x] += rs[threadIdx.x + st];
            rq[threadIdx.x] += rq[threadIdx.x + st];
        }
        __syncthreads();
    }
    if (threadIdx.x == 0) {
        part[(b*32 + chunk)*2]     = rs[0];
        part[(b*32 + chunk)*2 + 1] = rq[0];
    }
}

__global__ void ln_final(const float* __restrict__ part, float* __restrict__ stat)
{
    int b = blockIdx.x;
    float s = part[(b*32 + threadIdx.x)*2];
    float q = part[(b*32 + threadIdx.x)*2 + 1];
    for (int o = 16; o > 0; o >>= 1) {
        s += __shfl_down_sync(0xffffffffu, s, o);
        q += __shfl_down_sync(0xffffffffu, q, o);
    }
    if (threadIdx.x == 0) {
        float mean = s / (float)PERB;
        float var  = q / (float)PERB - mean * mean;
        stat[b*2] = mean; stat[b*2 + 1] = rsqrtf(var + 1e-5f);
    }
}

__global__ void ln_apply(const float* __restrict__ X, const float* __restrict__ g,
                         const float* __restrict__ bt, const float* __restrict__ stat,
                         float* __restrict__ out)
{
    long i4  = (long)blockIdx.x * blockDim.x + threadIdx.x;
    long idx = i4 * 4;
    int  b   = (int)(idx / PERB);
    long gi  = idx % PERB;
    float mean = stat[b*2], rstd = stat[b*2 + 1];
    float4 x  = *(const float4*)(X + idx);
    float4 gg = *(const float4*)(g + gi);
    float4 bb = *(const float4*)(bt + gi);
    float4 o;
    o.x = (x.x - mean) * rstd * gg.x + bb.x;
    o.y = (x.y - mean) * rstd * gg.y + bb.y;
    o.z = (x.z - mean) * rstd * gg.z + bb.z;
    o.w = (x.w - mean) * rstd * gg.w + bb.w;
    *(float4*)(out + idx) = o;
}

__global__ void copy_f4(const float* __restrict__ src, float* __restrict__ dst)
{
    long i = (long)blockIdx.x * blockDim.x + threadIdx.x;
    ((float4*)dst)[i] = ((const float4*)src)[i];
}

// ---------------- host orchestration ----------------
extern "C" void kernel_launch(void* const* d_in, const int* in_sizes, int n_in,
                              void* d_out, int out_size)
{
    (void)in_sizes; (void)n_in; (void)out_size;
    const float* mem   = (const float*)d_in[0];
    const float* y_in  = (const float*)d_in[1];
    const float* Wq_sa = (const float*)d_in[2];
    const float* bq_sa = (const float*)d_in[3];
    const float* Wk_sa = (const float*)d_in[4];
    const float* bk_sa = (const float*)d_in[5];
    const float* Wv_sa = (const float*)d_in[6];
    const float* bv_sa = (const float*)d_in[7];
    const float* Wo_sa = (const float*)d_in[8];
    const float* bo_sa = (const float*)d_in[9];
    const float* Wq_x  = (const float*)d_in[10];
    const float* bq_x  = (const float*)d_in[11];
    const float* Wk_x  = (const float*)d_in[12];
    const float* bk_x  = (const float*)d_in[13];
    const float* Wv_x  = (const float*)d_in[14];
    const float* bv_x  = (const float*)d_in[15];
    const float* Wo_x  = (const float*)d_in[16];
    const float* bo_x  = (const float*)d_in[17];
    const float* E1    = (const float*)d_in[18];
    const float* D1    = (const float*)d_in[19];
    const float* E2    = (const float*)d_in[20];
    const float* D2    = (const float*)d_in[21];
    const float* g1    = (const float*)d_in[22];
    const float* b1    = (const float*)d_in[23];
    const float* g2    = (const float*)d_in[24];
    const float* b2    = (const float*)d_in[25];
    const float* g3    = (const float*)d_in[26];
    const float* b3    = (const float*)d_in[27];
    float* out = (float*)d_out;

    float *yp,*qkv,*qx,*kv,*zz,*hid,*w1,*w2,*wp,*bp,*qm,*qz,*km,*kz,*bm,*part,*stat;
    bf16 *ah,*al,*bh,*bl;
    cudaGetSymbolAddress((void**)&yp,   g_y);
    cudaGetSymbolAddress((void**)&qkv,  g_qkv);
    cudaGetSymbolAddress((void**)&qx,   g_qx);
    cudaGetSymbolAddress((void**)&kv,   g_kv);
    cudaGetSymbolAddress((void**)&zz,   g_zz);
    cudaGetSymbolAddress((void**)&hid,  g_hid);
    cudaGetSymbolAddress((void**)&w1,   g_w1);
    cudaGetSymbolAddress((void**)&w2,   g_w2);
    cudaGetSymbolAddress((void**)&wp,   g_wp);
    cudaGetSymbolAddress((void**)&bp,   g_bp);
    cudaGetSymbolAddress((void**)&qm,   g_qm);
    cudaGetSymbolAddress((void**)&qz,   g_qz);
    cudaGetSymbolAddress((void**)&km,   g_km);
    cudaGetSymbolAddress((void**)&kz,   g_kz);
    cudaGetSymbolAddress((void**)&bm,   g_bm);
    cudaGetSymbolAddress((void**)&part, g_part);
    cudaGetSymbolAddress((void**)&stat, g_stat);
    cudaGetSymbolAddress((void**)&ah,   g_ah);
    cudaGetSymbolAddress((void**)&al,   g_al);
    cudaGetSymbolAddress((void**)&bh,   g_bh);
    cudaGetSymbolAddress((void**)&bl,   g_bl);

    #define SPLIT(p, n)  splitf<<<((n)/8 + 255)/256, 256>>>(p, ah, al, (n)/8)
    #define TSPL(p, K, N) tsplit<<<dim3((K)/32, (N)/32), dim3(32,8)>>>(p, K, N, bh, bl)

    copy_f4<<<TOK*DDIM/4/256, 256>>>(y_in, yp);

    // ===== masked self-attention =====
    pack_qkv<<<(DDIM*384 + 255)/256, 256>>>(Wq_sa, Wk_sa, Wv_sa, bq_sa, bk_sa, bv_sa, wp, bp);
    TSPL(wp, DDIM, 384);
    SPLIT(yp, TOK*DDIM);
    mma_gemm<128,128,64,32><<<dim3(3, TOK/128), 256>>>(
        ah, al, bh, bl, DDIM, qkv, 384, bp, nullptr, 0);
    colstat<<<dim3(128, BB), 256>>>(qkv, 384,   0, ST, 1, qm, qz);
    colstat<<<dim3(128, BB), 256>>>(qkv, 384, 128, ST, 0, km, kz);
    bm_kernel<<<16, 256>>>(qkv, 384, 128, qkv, 384, 256, ST, km, kz, bm);
    z_kernel<<<TOK/16, 256>>>(qkv, 384, bm, qm, qz, zz, 1);
    TSPL(Wo_sa, 128, DDIM);
    SPLIT(zz, TOK*128);
    mma_gemm<128,128,64,32><<<dim3(4, TOK/128), 256>>>(
        ah, al, bh, bl, 128, yp, DDIM, bo_sa, yp, 0);
    ln_part<<<dim3(32, BB), 256>>>(yp, part);
    ln_final<<<BB, 32>>>(part, stat);
    ln_apply<<<TOK*DDIM/4/256, 256>>>(yp, g1, b1, stat, yp);

    // ===== cross-attention =====
    pack_qkv<<<(DDIM*384 + 255)/256, 256>>>(Wq_x, Wk_x, Wv_x, bq_x, bk_x, bv_x, wp, bp);
    TSPL(wp, DDIM, 384);
    SPLIT(yp, TOK*DDIM);
    mma_gemm<128,128,64,32><<<dim3(1, TOK/128), 256>>>(
        ah, al, bh, bl, DDIM, qx, 128, bp, nullptr, 0);              // Q
    SPLIT(mem, TOKM*DDIM);
    mma_gemm<128,128,64,32><<<dim3(2, TOKM/128), 256>>>(
        ah, al, bh + 128*DDIM, bl + 128*DDIM, DDIM, kv, 256, bp + 128, nullptr, 0); // K,V
    colstat<<<dim3(128, BB), 256>>>(qx, 128, 0, ST,  0, qm, qz);
    colstat<<<dim3(128, BB), 256>>>(kv, 256, 0, SMM, 0, km, kz);
    bm_kernel<<<16, 256>>>(kv, 256, 0, kv, 256, 128, SMM, km, kz, bm);
    z_kernel<<<TOK/16, 256>>>(qx, 128, bm, qm, qz, zz, 0);
    TSPL(Wo_x, 128, DDIM);
    SPLIT(zz, TOK*128);
    mma_gemm<128,128,64,32><<<dim3(4, TOK/128), 256>>>(
        ah, al, bh, bl, 128, yp, DDIM, bo_x, yp, 0);
    ln_part<<<dim3(32, BB), 256>>>(yp, part);
    ln_final<<<BB, 32>>>(part, stat);
    ln_apply<<<TOK*DDIM/4/256, 256>>>(yp, g2, b2, stat, yp);

    // ===== LFFN (fused bottleneck weights) =====
    SPLIT(E1, DDIM*ST);
    TSPL(D1, ST, DHI);
    mma_gemm<64,64,32,32><<<dim3(DHI/64, DDIM/64), 128>>>(
        ah, al, bh, bl, ST, w1, DHI, nullptr, nullptr, 0);           // W1 = E1@D1
    SPLIT(E2, DHI*ST);
    TSPL(D2, ST, DDIM);
    mma_gemm<64,64,32,32><<<dim3(DDIM/64, DHI/64), 128>>>(
        ah, al, bh, bl, ST, w2, DDIM, nullptr, nullptr, 0);          // W2 = E2@D2
    SPLIT(yp, TOK*DDIM);
    TSPL(w1, DDIM, DHI);
    mma_gemm<128,128,64,32><<<dim3(DHI/128, TOK/128), 256>>>(
        ah, al, bh, bl, DDIM, hid, DHI, nullptr, nullptr, 1);        // swish
    SPLIT(hid, TOK*DHI);
    TSPL(w2, DHI, DDIM);
    mma_gemm<128,128,64,32><<<dim3(DDIM/128, TOK/128), 256>>>(
        ah, al, bh, bl, DHI, yp, DDIM, nullptr, yp, 0);              // +residual
    ln_part<<<dim3(32, BB), 256>>>(yp, part);
    ln_final<<<BB, 32>>>(part, stat);
    ln_apply<<<TOK*DDIM/4/256, 256>>>(yp, g3, b3, stat, out);

    #undef SPLIT
    #undef TSPL
}

// round 13
// speedup vs baseline: 2.2806x; 1.4789x over previous
#include <cuda_runtime.h>
#include <cuda_bf16.h>
#include <cstdint>
typedef __nv_bfloat16 bf16;

#define INV_DQ4 0.35355339059327373f
#define BB   8
#define ST   2048
#define SMM  1024
#define DDIM 512
#define DHI  1024
#define TOK  16384
#define TOKM 8192
#define PERB (ST*DDIM)

// ---------------- scratch ----------------
__device__ float g_y[TOK*DDIM];
__device__ float g_qkv[TOK*384];
__device__ float g_qx[TOK*128];
__device__ float g_kv[TOKM*256];
__device__ float g_wp[DDIM*384];
__device__ float g_bp[384];
__device__ float g_pm[BB*8*128], g_pz[BB*8*128];
__device__ float g_qm[BB*128], g_qz[BB*128];
__device__ float g_km[BB*128], g_kz[BB*128];
__device__ float g_bm[16*4096];
__device__ float g_bmp[16*8*4096];
__device__ float g_part[BB*32*2];
__device__ float g_stat[BB*2];
__device__ bf16  g_ah[TOK*DDIM], g_al[TOK*DDIM];   // A-side activations hi/lo
__device__ bf16  g_bh[DHI*ST],   g_bl[DHI*ST];     // B-side weights hi/lo
__device__ bf16  g_zh[TOK*128],  g_zl[TOK*128];    // Z hi/lo
__device__ bf16  g_hh[TOK*DHI],  g_hl[TOK*DHI];    // hidden hi/lo
__device__ bf16  g_w1h[DHI*DDIM], g_w1l[DHI*DDIM]; // W1^T hi/lo [DHI][DDIM]
__device__ bf16  g_w2h[DDIM*DHI], g_w2l[DDIM*DHI]; // W2^T hi/lo [DDIM][DHI]

// ---------------- split: fp32 -> bf16 hi/lo (elementwise) ----------------
__global__ void splitf(const float* __restrict__ src, bf16* __restrict__ hi,
                       bf16* __restrict__ lo, int n8)
{
    int i = blockIdx.x * 256 + threadIdx.x;
    if (i >= n8) return;
    float4 a = ((const float4*)src)[(long)i*2];
    float4 b = ((const float4*)src)[(long)i*2 + 1];
    float v[8] = {a.x,a.y,a.z,a.w,b.x,b.y,b.z,b.w};
    bf16 h[8], l[8];
    #pragma unroll
    for (int k = 0; k < 8; k++) {
        h[k] = __float2bfloat16(v[k]);
        l[k] = __float2bfloat16(v[k] - __bfloat162float(h[k]));
    }
    ((uint4*)hi)[i] = *(uint4*)h;
    ((uint4*)lo)[i] = *(uint4*)l;
}

// W[K][N] fp32 -> T[N][K] bf16 hi/lo  (K,N multiples of 32)
__global__ void tsplit(const float* __restrict__ W, int K, int N,
                       bf16* __restrict__ Th, bf16* __restrict__ Tl)
{
    __shared__ float t[32][33];
    int k0 = blockIdx.x * 32, n0 = blockIdx.y * 32;
    for (int i = threadIdx.y; i < 32; i += 8)
        t[i][threadIdx.x] = W[(long)(k0 + i) * N + n0 + threadIdx.x];
    __syncthreads();
    for (int i = threadIdx.y; i < 32; i += 8) {
        float v = t[threadIdx.x][i];
        bf16 h = __float2bfloat16(v);
        long o = (long)(n0 + i) * K + k0 + threadIdx.x;
        Th[o] = h;
        Tl[o] = __float2bfloat16(v - __bfloat162float(h));
    }
}

// ---------------- bf16-split tensor-core GEMM (ldmatrix + swizzle) -------
#define MMA_BF16(d, a, b) asm volatile( \
    "mma.sync.aligned.m16n8k16.row.col.f32.bf16.bf16.f32 " \
    "{%0,%1,%2,%3}, {%4,%5,%6,%7}, {%8,%9}, {%0,%1,%2,%3};" \
    : "+f"(d[0]), "+f"(d[1]), "+f"(d[2]), "+f"(d[3]) \
    : "r"(a[0]), "r"(a[1]), "r"(a[2]), "r"(a[3]), "r"(b[0]), "r"(b[1]))

#define LDSM4(R, a) asm volatile( \
    "ldmatrix.sync.aligned.m8n8.x4.shared.b16 {%0,%1,%2,%3}, [%4];" \
    : "=r"((R)[0]), "=r"((R)[1]), "=r"((R)[2]), "=r"((R)[3]) : "r"(a))

// C[M,N] = (Ah+Al)[M,K] @ (Bh+Bl)[N,K]^T ; K % 32 == 0.
// smem row (128B): chunks 0-3 = hi(32 bf16), 4-7 = lo; chunk ^= (row&7).
// OUT==0: fp32 C (+bias/act/res). OUT==1: bf16 hi/lo outputs Ch/Cl (+act).
template<int BM, int BN, int WM, int WN, int OUT>
__global__ void __launch_bounds__((BM/WM)*(BN/WN)*32) mma_gemm(
    const bf16* __restrict__ Ah, const bf16* __restrict__ Al,
    const bf16* __restrict__ Bh, const bf16* __restrict__ Bl,
    int K, float* __restrict__ C, bf16* __restrict__ Ch, bf16* __restrict__ Cl,
    int ldc, const float* __restrict__ bias, const float* __restrict__ res, int act)
{
    constexpr int NWN = BN / WN;
    constexpr int NT  = (BM/WM) * NWN * 32;
    constexpr int MT  = WM / 16, NTL = WN / 8;
    __shared__ __align__(128) uint4 sA[BM*8];
    __shared__ __align__(128) uint4 sB[BN*8];
    const int tid = threadIdx.x, wid = tid >> 5, lane = tid & 31;
    const int wm = wid / NWN, wn = wid % NWN;
    const int lr8 = lane & 7, g = lane >> 3;
    const int lq = lane & 3, lr = lane >> 2;
    const long row0 = (long)blockIdx.y * BM;
    const long col0 = (long)blockIdx.x * BN;
    const uint32_t saA = (uint32_t)__cvta_generic_to_shared(sA);
    const uint32_t saB = (uint32_t)__cvta_generic_to_shared(sB);
    constexpr int ITA = (BM*4) / NT, ITB = (BN*4) / NT;
    uint4 rah[ITA], ral[ITA], rbh[ITB], rbl[ITB];

    auto ldg = [&](int k0) {
        #pragma unroll
        for (int i = 0; i < ITA; i++) {
            int idx = tid + i*NT;
            long off = (row0 + (idx>>2)) * (long)K + k0 + ((idx&3)<<3);
            rah[i] = *(const uint4*)(Ah + off);
            ral[i] = *(const uint4*)(Al + off);
        }
        #pragma unroll
        for (int i = 0; i < ITB; i++) {
            int idx = tid + i*NT;
            long off = (col0 + (idx>>2)) * (long)K + k0 + ((idx&3)<<3);
            rbh[i] = *(const uint4*)(Bh + off);
            rbl[i] = *(const uint4*)(Bl + off);
        }
    };
    auto sts = [&]() {
        #pragma unroll
        for (int i = 0; i < ITA; i++) {
            int idx = tid + i*NT;
            int row = idx >> 2, c = idx & 3;
            int w = row*8 + (c ^ (row & 7));
            sA[w] = rah[i]; sA[w ^ 4] = ral[i];
        }
        #pragma unroll
        for (int i = 0; i < ITB; i++) {
            int idx = tid + i*NT;
            int row = idx >> 2, c = idx & 3;
            int w = row*8 + (c ^ (row & 7));
            sB[w] = rbh[i]; sB[w ^ 4] = rbl[i];
        }
    };

    float acc[MT][NTL][4];
    #pragma unroll
    for (int i = 0; i < MT; i++)
        #pragma unroll
        for (int j = 0; j < NTL; j++) {
            acc[i][j][0]=0.f; acc[i][j][1]=0.f; acc[i][j][2]=0.f; acc[i][j][3]=0.f;
        }

    auto compute = [&]() {
        #pragma unroll
        for (int ks = 0; ks < 2; ks++) {
            uint32_t afh[MT][4], afl[MT][4], bfh[NTL][2], bfl[NTL][2];
            #pragma unroll
            for (int i = 0; i < MT; i++) {
                int row = wm*WM + i*16 + ((g & 1) << 3) + lr8;
                int ch  = (ks << 1) + (g >> 1);
                uint32_t ad = saA + row*128 + ((ch ^ lr8) << 4);
                LDSM4(afh[i], ad);
                LDSM4(afl[i], ad ^ 64u);
            }
            #pragma unroll
            for (int jj = 0; jj < NTL/2; jj++) {
                int row = wn*WN + jj*16 + ((g >> 1) << 3) + lr8;
                int ch  = (ks << 1) + (g & 1);
                uint32_t ad = saB + row*128 + ((ch ^ lr8) << 4);
                uint32_t t[4];
                LDSM4(t, ad);
                bfh[2*jj][0]=t[0]; bfh[2*jj][1]=t[1];
                bfh[2*jj+1][0]=t[2]; bfh[2*jj+1][1]=t[3];
                LDSM4(t, ad ^ 64u);
                bfl[2*jj][0]=t[0]; bfl[2*jj][1]=t[1];
                bfl[2*jj+1][0]=t[2]; bfl[2*jj+1][1]=t[3];
            }
            #pragma unroll
            for (int i = 0; i < MT; i++)
                #pragma unroll
                for (int j = 0; j < NTL; j++) {
                    MMA_BF16(acc[i][j], afh[i], bfh[j]);
                    MMA_BF16(acc[i][j], afh[i], bfl[j]);
                    MMA_BF16(acc[i][j], afl[i], bfh[j]);
                }
        }
    };

    ldg(0); sts(); __syncthreads();
    for (int k0 = 32; k0 < K; k0 += 32) {
        ldg(k0);
        compute();
        __syncthreads();
        sts();
        __syncthreads();
    }
    compute();

    #pragma unroll
    for (int i = 0; i < MT; i++) {
        int r = (int)row0 + wm*WM + i*16 + lr;
        #pragma unroll
        for (int j = 0; j < NTL; j++) {
            int cb = (int)col0 + wn*WN + j*8 + 2*lq;
            float v[4] = {acc[i][j][0], acc[i][j][1], acc[i][j][2], acc[i][j][3]};
            if (bias) { float b0 = bias[cb], b1 = bias[cb+1];
                        v[0]+=b0; v[1]+=b1; v[2]+=b0; v[3]+=b1; }
            if (act) {
                #pragma unroll
                for (int q = 0; q < 4; q++) v[q] = v[q] / (1.f + __expf(-v[q]));
            }
            long o0 = (long)r*ldc + cb, o1 = o0 + 8L*ldc;
            if (OUT == 0) {
                if (res) { v[0]+=res[o0]; v[1]+=res[o0+1]; v[2]+=res[o1]; v[3]+=res[o1+1]; }
                *(float2*)(C + o0) = make_float2(v[0], v[1]);
                *(float2*)(C + o1) = make_float2(v[2], v[3]);
            } else {
                long oo[4] = {o0, o0+1, o1, o1+1};
                #pragma unroll
                for (int q = 0; q < 4; q++) {
                    bf16 h = __float2bfloat16(v[q]);
                    Ch[oo[q]] = h;
                    Cl[oo[q]] = __float2bfloat16(v[q] - __bfloat162float(h));
                }
            }
        }
    }
}

// ---------------- QKV weight packing ----------------
__global__ void pack_qkv(const float* __restrict__ Wq, const float* __restrict__ Wk,
                         const float* __restrict__ Wv, const float* __restrict__ bq,
                         const float* __restrict__ bk, const float* __restrict__ bv,
                         float* __restrict__ wp, float* __restrict__ bp)
{
    int idx = blockIdx.x * blockDim.x + threadIdx.x;
    if (idx < DDIM * 384) {
        int d = idx / 384, j = idx % 384;
        int p = j >> 7, jj = j & 127;
        int h = jj >> 6, e = jj & 63;
        const float* src = (p == 0) ? Wq : (p == 1) ? Wk : Wv;
        wp[idx] = src[((long)h * DDIM + d) * 64 + e];
    }
    if (idx < 384) {
        int p = idx >> 7, jj = idx & 127;
        const float* sb = (p == 0) ? bq : (p == 1) ? bk : bv;
        bp[idx] = sb[jj];
    }
}

// ---------------- coalesced column softmax stats (online) ----------------
__global__ void colpart(const float* __restrict__ X, int ld, int coloff, int S,
                        int mask, float* __restrict__ pm, float* __restrict__ pz)
{
    int chunk = blockIdx.x, b = blockIdx.y;
    int R = S >> 3;
    int rgrp = threadIdx.x >> 5, cg = threadIdx.x & 31;
    const float* base = X + ((long)(b*S + chunk*R + rgrp))*ld + coloff + cg*4;
    float m[4] = {-1e30f,-1e30f,-1e30f,-1e30f}, z[4] = {0.f,0.f,0.f,0.f};
    int e0 = (cg*4) & 63;
    for (int r = 0; r < R; r += 8) {
        float4 vv = *(const float4*)(base + (long)r*ld);
        int s = chunk*R + rgrp + r;
        float va[4] = {vv.x, vv.y, vv.z, vv.w};
        #pragma unroll
        for (int c = 0; c < 4; c++) {
            if (mask && (e0 + c) > s) continue;
            float val = va[c] * INV_DQ4;
            if (val <= m[c]) z[c] += __expf(val - m[c]);
            else { z[c] = z[c]*__expf(m[c] - val) + 1.f; m[c] = val; }
        }
    }
    __shared__ float sm_[8][128], sz_[8][128];
    #pragma unroll
    for (int c = 0; c < 4; c++) { sm_[rgrp][cg*4+c] = m[c]; sz_[rgrp][cg*4+c] = z[c]; }
    __syncthreads();
    if (threadIdx.x < 128) {
        int col = threadIdx.x;
        float M = -1e30f, Z = 0.f;
        #pragma unroll
        for (int l = 0; l < 8; l++) {
            float mi = sm_[l][col], zi = sz_[l][col];
            if (zi == 0.f) continue;
            if (mi <= M) Z += zi * __expf(mi - M);
            else { Z = Z*__expf(M - mi) + zi; M = mi; }
        }
        pm[(b*8 + chunk)*128 + col] = M;
        pz[(b*8 + chunk)*128 + col] = Z;
    }
}

__global__ void colmerge(const float* __restrict__ pm, const float* __restrict__ pz,
                         float* __restrict__ mo, float* __restrict__ zo)
{
    int b = blockIdx.x, col = threadIdx.x;
    float M = -1e30f, Z = 0.f;
    for (int c = 0; c < 8; c++) {
        float mi = pm[(b*8 + c)*128 + col], zi = pz[(b*8 + c)*128 + col];
        if (zi == 0.f) continue;
        if (mi <= M) Z += zi * __expf(mi - M);
        else { Z = Z*__expf(M - mi) + zi; M = mi; }
    }
    mo[b*128 + col] = M;
    zo[b*128 + col] = Z;
}

// ---------------- Bm partials over seq chunks ----------------
__global__ void __launch_bounds__(256) bmpart(
    const float* __restrict__ Kb, int ldk, int koff,
    const float* __restrict__ Vb, int ldv, int voff,
    int S, const float* __restrict__ km, float* __restrict__ bmp)
{
    int chunk = blockIdx.x, blk = blockIdx.y;   // blk = h*8+b
    int h = blk >> 3, b = blk & 7;
    int R = S >> 3;
    int tid = threadIdx.x;
    int e = tid >> 2, d0 = (tid & 3) * 16;
    __shared__ float Ks[64][64];
    __shared__ float Vs[64][64];
    float acc[16];
    #pragma unroll
    for (int i = 0; i < 16; i++) acc[i] = 0.f;
    float me = km[b*128 + h*64 + e];
    const float* kp = Kb + (long)(b*S + chunk*R) * ldk + koff + h*64;
    const float* vp = Vb + (long)(b*S + chunk*R) * ldv + voff + h*64;
    for (int t = 0; t < R/64; t++) {
        for (int idx = tid; idx < 64*16; idx += 256) {
            int r = idx >> 4, c4 = (idx & 15) << 2;
            *(float4*)&Ks[r][c4] = *(const float4*)(kp + (long)(t*64 + r)*ldk + c4);
            *(float4*)&Vs[r][c4] = *(const float4*)(vp + (long)(t*64 + r)*ldv + c4);
        }
        __syncthreads();
        #pragma unroll 4
        for (int s = 0; s < 64; s++) {
            float w = __expf(Ks[s][e] * INV_DQ4 - me);
            #pragma unroll
            for (int dd = 0; dd < 16; dd++) acc[dd] += w * Vs[s][d0 + dd];
        }
        __syncthreads();
    }
    float* outp = bmp + ((long)blk*8 + chunk)*4096 + e*64 + d0;
    #pragma unroll
    for (int dd = 0; dd < 16; dd++) outp[dd] = acc[dd];
}

__global__ void bm_reduce(const float* __restrict__ bmp, const float* __restrict__ kz,
                          float* __restrict__ bm)
{
    int gid = blockIdx.x * 256 + threadIdx.x;   // < 16*4096
    int blk = gid >> 12, r = gid & 4095;
    int h = blk >> 3, b = blk & 7, e = r >> 6;
    float s = 0.f;
    for (int c = 0; c < 8; c++) s += bmp[((long)blk*8 + c)*4096 + r];
    bm[(long)blk*4096 + r] = s / kz[b*128 + h*64 + e];
}

// ---------------- Z = A @ Bm  (emits bf16 hi/lo) ----------------
__global__ void __launch_bounds__(256) z_kernel(
    const float* __restrict__ Q, int ldq, const float* __restrict__ bm,
    const float* __restrict__ qm, const float* __restrict__ qz,
    bf16* __restrict__ Zh, bf16* __restrict__ Zl, int mask)
{
    __shared__ float Bs[2][64][64];
    __shared__ float qs[16][128];
    __shared__ float sm[128], siz[128];
    int tid = threadIdx.x;
    int row0 = blockIdx.x * 16;
    int b = row0 / ST;
    for (int idx = tid; idx < 2048; idx += 256) {
        int hh = idx >> 10, rr = (idx >> 4) & 63, c4 = (idx & 15) << 2;
        *(float4*)&Bs[hh][rr][c4] =
            *(const float4*)(bm + ((long)(hh*BB + b) * 64 + rr) * 64 + c4);
    }
    for (int idx = tid; idx < 512; idx += 256) {
        int rr = idx >> 5, c4 = (idx & 31) << 2;
        *(float4*)&qs[rr][c4] = *(const float4*)(Q + (long)(row0 + rr) * ldq + c4);
    }
    if (tid < 128) { sm[tid] = qm[b*128 + tid]; siz[tid] = 1.f / qz[b*128 + tid]; }
    __syncthreads();
    int rid = tid >> 4, sub = tid & 15;
    int h = sub >> 3, d0 = (sub & 7) * 8;
    int s = (row0 + rid) & (ST - 1);
    float acc[8];
    #pragma unroll
    for (int i = 0; i < 8; i++) acc[i] = 0.f;
    int elim = mask ? min(63, s) : 63;
    for (int e = 0; e <= elim; e++) {
        float w = __expf(qs[rid][h*64 + e] * INV_DQ4 - sm[h*64 + e]) * siz[h*64 + e];
        const float* bp = &Bs[h][e][d0];
        #pragma unroll
        for (int dd = 0; dd < 8; dd++) acc[dd] += w * bp[dd];
    }
    long o = (long)(row0 + rid) * 128 + h*64 + d0;
    #pragma unroll
    for (int dd = 0; dd < 8; dd++) {
        bf16 hh2 = __float2bfloat16(acc[dd]);
        Zh[o + dd] = hh2;
        Zl[o + dd] = __float2bfloat16(acc[dd] - __bfloat162float(hh2));
    }
}

// ---------------- LayerNorm (per batch over S*D) ----------------
__global__ void ln_part(const float* __restrict__ X, float* __restrict__ part)
{
    int b = blockIdx.y, chunk = blockIdx.x;
    const float4* p = (const float4*)(X + (long)b*PERB) + (long)chunk*8192 + threadIdx.x;
    float s = 0.f, q = 0.f;
    for (int k = 0; k < 32; k++) {
        float4 v = p[(long)k*256];
        s += v.x + v.y + v.z + v.w;
        q += v.x*v.x + v.y*v.y + v.z*v.z + v.w*v.w;
    }
    __shared__ float rs[256], rq[256];
    rs[threadIdx.x] = s; rq[threadIdx.x] = q; __syncthreads();
    for (int st = 128; st > 0; st >>= 1) {
        if (threadIdx.x < st) {
            rs[threadIdx.x] += rs[threadIdx.x + st];
            rq[threadIdx.x] += rq[threadIdx.x + st];
        }
        __syncthreads();
    }
    if (threadIdx.x == 0) {
        part[(b*32 + chunk)*2]     = rs[0];
        part[(b*32 + chunk)*2 + 1] = rq[0];
    }
}

__global__ void ln_final(const float* __restrict__ part, float* __restrict__ stat)
{
    int b = blockIdx.x;
    float s = part[(b*32 + threadIdx.x)*2];
    float q = part[(b*32 + threadIdx.x)*2 + 1];
    for (int o = 16; o > 0; o >>= 1) {
        s += __shfl_down_sync(0xffffffffu, s, o);
        q += __shfl_down_sync(0xffffffffu, q, o);
    }
    if (threadIdx.x == 0) {
        float mean = s / (float)PERB;
        float var  = q / (float)PERB - mean * mean;
        stat[b*2] = mean; stat[b*2 + 1] = rsqrtf(var + 1e-5f);
    }
}

// out fp32 (+ optional bf16 hi/lo split emit)
__global__ void ln_apply(const float* __restrict__ X, const float* __restrict__ g,
                         const float* __restrict__ bt, const float* __restrict__ stat,
                         float* __restrict__ out, bf16* __restrict__ oh,
                         bf16* __restrict__ ol)
{
    long i4  = (long)blockIdx.x * blockDim.x + threadIdx.x;
    long idx = i4 * 4;
    int  b   = (int)(idx / PERB);
    long gi  = idx % PERB;
    float mean = stat[b*2], rstd = stat[b*2 + 1];
    float4 x  = *(const float4*)(X + idx);
    float4 gg = *(const float4*)(g + gi);
    float4 bb = *(const float4*)(bt + gi);
    float4 o;
    o.x = (x.x - mean) * rstd * gg.x + bb.x;
    o.y = (x.y - mean) * rstd * gg.y + bb.y;
    o.z = (x.z - mean) * rstd * gg.z + bb.z;
    o.w = (x.w - mean) * rstd * gg.w + bb.w;
    *(float4*)(out + idx) = o;
    if (oh) {
        float v[4] = {o.x, o.y, o.z, o.w};
        bf16 h[4], l[4];
        #pragma unroll
        for (int k = 0; k < 4; k++) {
            h[k] = __float2bfloat16(v[k]);
            l[k] = __float2bfloat16(v[k] - __bfloat162float(h[k]));
        }
        ((uint2*)oh)[i4] = *(uint2*)h;
        ((uint2*)ol)[i4] = *(uint2*)l;
    }
}

// ---------------- host orchestration ----------------
extern "C" void kernel_launch(void* const* d_in, const int* in_sizes, int n_in,
                              void* d_out, int out_size)
{
    (void)in_sizes; (void)n_in; (void)out_size;
    const float* mem   = (const float*)d_in[0];
    const float* y_in  = (const float*)d_in[1];
    const float* Wq_sa = (const float*)d_in[2];
    const float* bq_sa = (const float*)d_in[3];
    const float* Wk_sa = (const float*)d_in[4];
    const float* bk_sa = (const float*)d_in[5];
    const float* Wv_sa = (const float*)d_in[6];
    const float* bv_sa = (const float*)d_in[7];
    const float* Wo_sa = (const float*)d_in[8];
    const float* bo_sa = (const float*)d_in[9];
    const float* Wq_x  = (const float*)d_in[10];
    const float* bq_x  = (const float*)d_in[11];
    const float* Wk_x  = (const float*)d_in[12];
    const float* bk_x  = (const float*)d_in[13];
    const float* Wv_x  = (const float*)d_in[14];
    const float* bv_x  = (const float*)d_in[15];
    const float* Wo_x  = (const float*)d_in[16];
    const float* bo_x  = (const float*)d_in[17];
    const float* E1    = (const float*)d_in[18];
    const float* D1    = (const float*)d_in[19];
    const float* E2    = (const float*)d_in[20];
    const float* D2    = (const float*)d_in[21];
    const float* g1    = (const float*)d_in[22];
    const float* b1    = (const float*)d_in[23];
    const float* g2    = (const float*)d_in[24];
    const float* b2    = (const float*)d_in[25];
    const float* g3    = (const float*)d_in[26];
    const float* b3    = (const float*)d_in[27];
    float* out = (float*)d_out;

    float *yp,*qkv,*qx,*kv,*wp,*bp,*pm,*pz,*qm,*qz,*km,*kz,*bm,*bmp,*part,*stat;
    bf16 *ah,*al,*bh,*bl,*zh,*zl,*hh,*hl,*w1h,*w1l,*w2h,*w2l;
    cudaGetSymbolAddress((void**)&yp,   g_y);
    cudaGetSymbolAddress((void**)&qkv,  g_qkv);
    cudaGetSymbolAddress((void**)&qx,   g_qx);
    cudaGetSymbolAddress((void**)&kv,   g_kv);
    cudaGetSymbolAddress((void**)&wp,   g_wp);
    cudaGetSymbolAddress((void**)&bp,   g_bp);
    cudaGetSymbolAddress((void**)&pm,   g_pm);
    cudaGetSymbolAddress((void**)&pz,   g_pz);
    cudaGetSymbolAddress((void**)&qm,   g_qm);
    cudaGetSymbolAddress((void**)&qz,   g_qz);
    cudaGetSymbolAddress((void**)&km,   g_km);
    cudaGetSymbolAddress((void**)&kz,   g_kz);
    cudaGetSymbolAddress((void**)&bm,   g_bm);
    cudaGetSymbolAddress((void**)&bmp,  g_bmp);
    cudaGetSymbolAddress((void**)&part, g_part);
    cudaGetSymbolAddress((void**)&stat, g_stat);
    cudaGetSymbolAddress((void**)&ah,   g_ah);
    cudaGetSymbolAddress((void**)&al,   g_al);
    cudaGetSymbolAddress((void**)&bh,   g_bh);
    cudaGetSymbolAddress((void**)&bl,   g_bl);
    cudaGetSymbolAddress((void**)&zh,   g_zh);
    cudaGetSymbolAddress((void**)&zl,   g_zl);
    cudaGetSymbolAddress((void**)&hh,   g_hh);
    cudaGetSymbolAddress((void**)&hl,   g_hl);
    cudaGetSymbolAddress((void**)&w1h,  g_w1h);
    cudaGetSymbolAddress((void**)&w1l,  g_w1l);
    cudaGetSymbolAddress((void**)&w2h,  g_w2h);
    cudaGetSymbolAddress((void**)&w2l,  g_w2l);

    // ===== LFFN fused-weight prep (independent of y) =====
    // W1^T[DHI][DDIM] = D1^T @ E1 : A = D1^T, B = E1 (rows = ddim, k = s)
    tsplit<<<dim3(ST/32, DHI/32), dim3(32,8)>>>(D1, ST, DHI, ah, al);
    splitf<<<DDIM*ST/8/256, 256>>>(E1, bh, bl, DDIM*ST/8);
    mma_gemm<64,64,32,32,1><<<dim3(DDIM/64, DHI/64), 128>>>(
        ah, al, bh, bl, ST, nullptr, w1h, w1l, DDIM, nullptr, nullptr, 0);
    // W2^T[DDIM][DHI] = D2^T @ E2
    tsplit<<<dim3(ST/32, DDIM/32), dim3(32,8)>>>(D2, ST, DDIM, ah, al);
    splitf<<<DHI*ST/8/256, 256>>>(E2, bh, bl, DHI*ST/8);
    mma_gemm<64,64,32,32,1><<<dim3(DHI/64, DDIM/64), 128>>>(
        ah, al, bh, bl, ST, nullptr, w2h, w2l, DHI, nullptr, nullptr, 0);

    // ===== masked self-attention =====
    pack_qkv<<<(DDIM*384 + 255)/256, 256>>>(Wq_sa, Wk_sa, Wv_sa, bq_sa, bk_sa, bv_sa, wp, bp);
    tsplit<<<dim3(DDIM/32, 384/32), dim3(32,8)>>>(wp, DDIM, 384, bh, bl);
    splitf<<<TOK*DDIM/8/256, 256>>>(y_in, ah, al, TOK*DDIM/8);
    mma_gemm<128,128,64,32,0><<<dim3(3, TOK/128), 256>>>(
        ah, al, bh, bl, DDIM, qkv, nullptr, nullptr, 384, bp, nullptr, 0);
    colpart<<<dim3(8, BB), 256>>>(qkv, 384,   0, ST, 1, pm, pz);
    colmerge<<<BB, 128>>>(pm, pz, qm, qz);
    colpart<<<dim3(8, BB), 256>>>(qkv, 384, 128, ST, 0, pm, pz);
    colmerge<<<BB, 128>>>(pm, pz, km, kz);
    bmpart<<<dim3(8, 16), 256>>>(qkv, 384, 128, qkv, 384, 256, ST, km, bmp);
    bm_reduce<<<16*4096/256, 256>>>(bmp, kz, bm);
    z_kernel<<<TOK/16, 256>>>(qkv, 384, bm, qm, qz, zh, zl, 1);
    tsplit<<<dim3(128/32, DDIM/32), dim3(32,8)>>>(Wo_sa, 128, DDIM, bh, bl);
    mma_gemm<128,128,64,32,0><<<dim3(4, TOK/128), 256>>>(
        zh, zl, bh, bl, 128, yp, nullptr, nullptr, DDIM, bo_sa, y_in, 0);
    ln_part<<<dim3(32, BB), 256>>>(yp, part);
    ln_final<<<BB, 32>>>(part, stat);
    ln_apply<<<TOK*DDIM/4/256, 256>>>(yp, g1, b1, stat, yp, ah, al);

    // ===== cross-attention =====
    pack_qkv<<<(DDIM*384 + 255)/256, 256>>>(Wq_x, Wk_x, Wv_x, bq_x, bk_x, bv_x, wp, bp);
    tsplit<<<dim3(DDIM/32, 384/32), dim3(32,8)>>>(wp, DDIM, 384, bh, bl);
    mma_gemm<128,128,64,32,0><<<dim3(1, TOK/128), 256>>>(
        ah, al, bh, bl, DDIM, qx, nullptr, nullptr, 128, bp, nullptr, 0);   // Q
    splitf<<<TOKM*DDIM/8/256, 256>>>(mem, ah, al, TOKM*DDIM/8);
    mma_gemm<128,128,64,32,0><<<dim3(2, TOKM/128), 256>>>(
        ah, al, bh + 128*DDIM, bl + 128*DDIM, DDIM, kv, nullptr, nullptr,
        256, bp + 128, nullptr, 0);                                         // K,V
    colpart<<<dim3(8, BB), 256>>>(qx, 128, 0, ST,  0, pm, pz);
    colmerge<<<BB, 128>>>(pm, pz, qm, qz);
    colpart<<<dim3(8, BB), 256>>>(kv, 256, 0, SMM, 0, pm, pz);
    colmerge<<<BB, 128>>>(pm, pz, km, kz);
    bmpart<<<dim3(8, 16), 256>>>(kv, 256, 0, kv, 256, 128, SMM, km, bmp);
    bm_reduce<<<16*4096/256, 256>>>(bmp, kz, bm);
    z_kernel<<<TOK/16, 256>>>(qx, 128, bm, qm, qz, zh, zl, 0);
    tsplit<<<dim3(128/32, DDIM/32), dim3(32,8)>>>(Wo_x, 128, DDIM, bh, bl);
    mma_gemm<128,128,64,32,0><<<dim3(4, TOK/128), 256>>>(
        zh, zl, bh, bl, 128, yp, nullptr, nullptr, DDIM, bo_x, yp, 0);
    ln_part<<<dim3(32, BB), 256>>>(yp, part);
    ln_final<<<BB, 32>>>(part, stat);
    ln_apply<<<TOK*DDIM/4/256, 256>>>(yp, g2, b2, stat, yp, ah, al);

    // ===== LFFN =====
    mma_gemm<128,128,64,32,1><<<dim3(DHI/128, TOK/128), 256>>>(
        ah, al, w1h, w1l, DDIM, nullptr, hh, hl, DHI, nullptr, nullptr, 1); // swish
    mma_gemm<128,128,64,32,0><<<dim3(4, TOK/128), 256>>>(
        hh, hl, w2h, w2l, DHI, yp, nullptr, nullptr, DDIM, nullptr, yp, 0);
    ln_part<<<dim3(32, BB), 256>>>(yp, part);
    ln_final<<<BB, 32>>>(part, stat);
    ln_apply<<<TOK*DDIM/4/256, 256>>>(yp, g3, b3, stat, out, nullptr, nullptr);
}